// round 4
// baseline (speedup 1.0000x reference)
#include <cuda_runtime.h>
#include <cuda_bf16.h>
#include <math.h>
#include <stdint.h>

// Problem constants (from reference): inputs [64,256,32,32] f32, embedding [1024,256] f32
// N = 64*32*32 = 65536 rows, D = 256, K = 1024
// Output layout assumed: [loss (1), q_out (64*256*32*32 = 16777216), perplexity (1)]

#define NROWS   65536
#define DDIM    256
#define KCODES  1024
#define BATCH   64
#define HWSZ    1024            // 32*32
#define QELEMS  16777216        // 64*256*1024

#define NEG_INF (-__int_as_float(0x7f800000))

// JAX threefry mode: 1 = partitionable (modern default), 0 = legacy split-counts
#define JAX_PARTITIONABLE 1

// ---------------- scratch (device globals; no allocation allowed) ----------------
__device__ float g_X[(size_t)NROWS * DDIM];        // transposed inputs [n][d]   (64 MB)
__device__ float g_S[(size_t)NROWS * KCODES];      // logits s = 2<x,e> - |e|^2  (256 MB)
__device__ float g_bnorm[KCODES];                  // |e_k|^2
__device__ float g_counts[KCODES];                 // hard-assignment counts
__device__ float g_entrow[NROWS];                  // per-row sum p*log p
__device__ int   g_idx[NROWS];                     // argmax index per row

// ---------------- threefry2x32 (JAX-exact) ----------------
__device__ __forceinline__ void threefry2x32(unsigned int x0, unsigned int x1,
                                             unsigned int& r0, unsigned int& r1) {
    const unsigned int k0 = 0u;
    const unsigned int k1 = 42u;
    const unsigned int k2 = 0u ^ 42u ^ 0x1BD11BDAu;
#define TFR(r) { x0 += x1; x1 = (x1 << (r)) | (x1 >> (32 - (r))); x1 ^= x0; }
    x0 += k0; x1 += k1;
    TFR(13) TFR(15) TFR(26) TFR(6)
    x0 += k1; x1 += k2 + 1u;
    TFR(17) TFR(29) TFR(16) TFR(24)
    x0 += k2; x1 += k0 + 2u;
    TFR(13) TFR(15) TFR(26) TFR(6)
    x0 += k0; x1 += k1 + 3u;
    TFR(17) TFR(29) TFR(16) TFR(24)
    x0 += k1; x1 += k2 + 4u;
    TFR(13) TFR(15) TFR(26) TFR(6)
    x0 += k2; x1 += k0 + 5u;
#undef TFR
    r0 = x0; r1 = x1;
}

// gumbel noise for flat element index e (row-major [N,K]), matching
// jax.random.uniform(key(42), (N,K), minval=1e-9, maxval=1.0) then -log(-log(u))
__device__ __forceinline__ float gumbel_at(unsigned int e) {
#if JAX_PARTITIONABLE
    unsigned int r0, r1;
    threefry2x32(0u, e, r0, r1);
    unsigned int bits = r0 ^ r1;
#else
    const unsigned int NH = (NROWS * (unsigned)KCODES) / 2u;  // 33554432
    unsigned int p = (e < NH) ? e : (e - NH);
    unsigned int r0, r1;
    threefry2x32(p, p + NH, r0, r1);
    unsigned int bits = (e < NH) ? r0 : r1;
#endif
    float f = __uint_as_float((bits >> 9) | 0x3f800000u) - 1.0f;   // [0,1)
    float u = fmaxf(1e-9f, f + 1e-9f);                              // (maxval-minval)==1.0f in fp32
    return -logf(-logf(u));
}

// ---------------- kernel 0: re-zero accumulators (graph replay safety) ----------------
__global__ void zero_kernel() {
    int t = threadIdx.x;
    if (t < KCODES) g_counts[t] = 0.0f;
}

// ---------------- kernel 1: transpose [b][d][hw] -> X[(b*1024+hw)][d] ----------------
__global__ void transpose_kernel(const float* __restrict__ in) {
    __shared__ float tile[32][33];
    int b   = blockIdx.z;
    int hw0 = blockIdx.x * 32;
    int d0  = blockIdx.y * 32;
    int tx = threadIdx.x, ty = threadIdx.y;
    const float* src = in + (size_t)b * (DDIM * HWSZ);
#pragma unroll
    for (int j = 0; j < 4; j++) {
        int d  = d0 + ty + j * 8;
        int hw = hw0 + tx;
        tile[ty + j * 8][tx] = src[(size_t)d * HWSZ + hw];
    }
    __syncthreads();
#pragma unroll
    for (int j = 0; j < 4; j++) {
        int hw = hw0 + ty + j * 8;
        int d  = d0 + tx;
        g_X[(size_t)(b * HWSZ + hw) * DDIM + d] = tile[tx][ty + j * 8];
    }
}

// ---------------- kernel 2: embedding row norms ----------------
__global__ void bnorm_kernel(const float* __restrict__ E) {
    __shared__ float red[256];
    int k = blockIdx.x, t = threadIdx.x;
    float v = E[(size_t)k * DDIM + t];
    red[t] = v * v;
    __syncthreads();
    for (int off = 128; off > 0; off >>= 1) {
        if (t < off) red[t] += red[t + off];
        __syncthreads();
    }
    if (t == 0) g_bnorm[k] = red[0];
}

// ---------------- kernel 3: SGEMM  S[n][k] = 2 * X[n]·E[k] - bnorm[k] ----------------
#define BM 128
#define BN 128
#define BKD 16
__global__ __launch_bounds__(256, 2)
void gemm_kernel(const float* __restrict__ E) {
    __shared__ float As[BKD][BM + 4];
    __shared__ float Bs[BKD][BN + 4];
    int tid = threadIdx.x;
    int tx = tid & 15;        // 0..15 -> n sub-tile
    int ty = tid >> 4;        // 0..15 -> m sub-tile
    int m0 = blockIdx.y * BM;
    int n0 = blockIdx.x * BN;

    float acc[8][8];
#pragma unroll
    for (int i = 0; i < 8; i++)
#pragma unroll
        for (int j = 0; j < 8; j++) acc[i][j] = 0.0f;

    for (int kt = 0; kt < DDIM; kt += BKD) {
#pragma unroll
        for (int q = 0; q < 2; q++) {
            int i4 = tid * 2 + q;          // 0..511
            int r  = i4 >> 2;              // 0..127
            int c  = (i4 & 3) * 4;         // 0,4,8,12
            float4 va = *reinterpret_cast<const float4*>(&g_X[(size_t)(m0 + r) * DDIM + kt + c]);
            As[c + 0][r] = va.x; As[c + 1][r] = va.y; As[c + 2][r] = va.z; As[c + 3][r] = va.w;
            float4 vb = *reinterpret_cast<const float4*>(&E[(size_t)(n0 + r) * DDIM + kt + c]);
            Bs[c + 0][r] = vb.x; Bs[c + 1][r] = vb.y; Bs[c + 2][r] = vb.z; Bs[c + 3][r] = vb.w;
        }
        __syncthreads();
#pragma unroll
        for (int kk = 0; kk < BKD; kk++) {
            float a[8], bb[8];
#pragma unroll
            for (int i = 0; i < 8; i++) a[i] = As[kk][ty * 8 + i];
#pragma unroll
            for (int j = 0; j < 8; j++) bb[j] = Bs[kk][tx * 8 + j];
#pragma unroll
            for (int i = 0; i < 8; i++)
#pragma unroll
                for (int j = 0; j < 8; j++) acc[i][j] = fmaf(a[i], bb[j], acc[i][j]);
        }
        __syncthreads();
    }
    // epilogue: s = 2*acc - bnorm[k]
#pragma unroll
    for (int i = 0; i < 8; i++) {
        int m = m0 + ty * 8 + i;
#pragma unroll
        for (int j = 0; j < 8; j++) {
            int nn = n0 + tx * 8 + j;
            g_S[(size_t)m * KCODES + nn] = fmaf(2.0f, acc[i][j], -g_bnorm[nn]);
        }
    }
}

// ---------------- kernel 4: per-row softmax-entropy + gumbel argmax ----------------
__global__ __launch_bounds__(256)
void epi_kernel() {
    int n = blockIdx.x;
    int t = threadIdx.x;
    const float* srow = g_S + (size_t)n * KCODES;

    float sv[4];
    float bestv = NEG_INF;
    int   besti = 0;
    float smax  = NEG_INF;
#pragma unroll
    for (int j = 0; j < 4; j++) {
        int k = t + j * 256;
        sv[j] = srow[k];
        float g = gumbel_at((unsigned int)n * (unsigned int)KCODES + (unsigned int)k);
        float y = sv[j] + g;
        if (y > bestv) { bestv = y; besti = k; }   // ascending k -> keeps first max
        smax = fmaxf(smax, sv[j]);
    }

    __shared__ float rv[256];
    __shared__ int   ri[256];
    __shared__ float rm[256];
    rv[t] = bestv; ri[t] = besti; rm[t] = smax;
    __syncthreads();
    for (int off = 128; off > 0; off >>= 1) {
        if (t < off) {
            float v2 = rv[t + off]; int i2 = ri[t + off];
            if (v2 > rv[t] || (v2 == rv[t] && i2 < ri[t])) { rv[t] = v2; ri[t] = i2; }
            rm[t] = fmaxf(rm[t], rm[t + off]);
        }
        __syncthreads();
    }
    float mrow = rm[0];
    int   bidx = ri[0];
    __syncthreads();

    float z = 0.0f, w = 0.0f;
#pragma unroll
    for (int j = 0; j < 4; j++) {
        float d = sv[j] - mrow;
        float e = expf(d);
        z += e;
        w += d * e;
    }
    rv[t] = z; rm[t] = w;
    __syncthreads();
    for (int off = 128; off > 0; off >>= 1) {
        if (t < off) { rv[t] += rv[t + off]; rm[t] += rm[t + off]; }
        __syncthreads();
    }
    if (t == 0) {
        float Z = rv[0], W = rm[0];
        g_entrow[n] = W / Z - logf(Z);
        g_idx[n] = bidx;
        atomicAdd(&g_counts[bidx], 1.0f);   // integer-valued float adds: exact & deterministic
    }
}

// ---------------- kernel 5: scatter q_out = embedding[idx], layout [b][d][hw] ----------------
__global__ __launch_bounds__(256)
void scatter_kernel(const float* __restrict__ E, float* __restrict__ qout) {
    int b  = blockIdx.y;
    int hw = blockIdx.x * 256 + threadIdx.x;
    int n  = b * HWSZ + hw;
    int row = g_idx[n];
    const float4* e4 = reinterpret_cast<const float4*>(E + (size_t)row * DDIM);
    float* outb = qout + (size_t)b * (DDIM * HWSZ) + hw;
#pragma unroll 4
    for (int d4 = 0; d4 < DDIM / 4; d4++) {
        float4 v = e4[d4];
        outb[(size_t)(d4 * 4 + 0) * HWSZ] = v.x;
        outb[(size_t)(d4 * 4 + 1) * HWSZ] = v.y;
        outb[(size_t)(d4 * 4 + 2) * HWSZ] = v.z;
        outb[(size_t)(d4 * 4 + 3) * HWSZ] = v.w;
    }
}

// ---------------- kernel 6: finalize loss + perplexity ----------------
__global__ __launch_bounds__(1024)
void finalize_kernel(float* __restrict__ out) {
    __shared__ double sh1[1024];
    __shared__ double sh2[1024];
    int t = threadIdx.x;
    double es = 0.0;
    for (int j = 0; j < NROWS / 1024; j++) es += (double)g_entrow[t + 1024 * j];
    float c = g_counts[t];
    float q = c * (1.0f / (float)NROWS);
    float term = q * logf(q + 1e-10f);
    sh1[t] = es;
    sh2[t] = (double)term;
    __syncthreads();
    for (int off = 512; off > 0; off >>= 1) {
        if (t < off) { sh1[t] += sh1[t + off]; sh2[t] += sh2[t + off]; }
        __syncthreads();
    }
    if (t == 0) {
        float loss = 0.25f * (float)(sh1[0] / (double)NROWS);
        float perp = expf(-(float)sh2[0]);
        out[0] = loss;                 // loss
        out[1 + QELEMS] = perp;        // perplexity
    }
}

// ---------------- launch ----------------
extern "C" void kernel_launch(void* const* d_in, const int* in_sizes, int n_in,
                              void* d_out, int out_size) {
    const float* inp = (const float*)d_in[0];   // [64,256,32,32]
    const float* emb = (const float*)d_in[1];   // [1024,256]
    float* out = (float*)d_out;                 // [1 + 16777216 + 1]

    zero_kernel<<<1, 1024>>>();
    transpose_kernel<<<dim3(HWSZ / 32, DDIM / 32, BATCH), dim3(32, 8)>>>(inp);
    bnorm_kernel<<<KCODES, 256>>>(emb);
    gemm_kernel<<<dim3(KCODES / BN, NROWS / BM), 256>>>(emb);
    epi_kernel<<<NROWS, 256>>>();
    scatter_kernel<<<dim3(HWSZ / 256, BATCH), 256>>>(emb, out + 1);
    finalize_kernel<<<1, 1024>>>(out);
}

// round 6
// speedup vs baseline: 1.6076x; 1.6076x over previous
#include <cuda_runtime.h>
#include <cuda_bf16.h>
#include <math.h>
#include <stdint.h>

// N = 64*32*32 = 65536 rows, D = 256, K = 1024
// Output layout: [loss (1), q_out (16777216), perplexity (1)]

#define NROWS   65536
#define DDIM    256
#define KCODES  1024
#define BATCH   64
#define HWSZ    1024
#define QELEMS  16777216

#define NEG_INF (-__int_as_float(0x7f800000))
#define JAX_PARTITIONABLE 1

// ---------------- scratch (device globals; no allocation allowed) ----------------
__device__ __nv_bfloat16 g_Xb[(size_t)NROWS * DDIM];   // bf16(x)         (32 MB)
__device__ __nv_bfloat16 g_Xs[(size_t)NROWS * DDIM];   // bf16(x - big)   (32 MB)
__device__ __nv_bfloat16 g_Eb[(size_t)KCODES * DDIM];
__device__ __nv_bfloat16 g_Es[(size_t)KCODES * DDIM];
__device__ float g_S[(size_t)NROWS * KCODES];          // logits          (256 MB)
__device__ float g_bnorm[KCODES];
__device__ float g_counts[KCODES];
__device__ float g_entrow[NROWS];
__device__ int   g_idx[NROWS];

// ---------------- helpers ----------------
__device__ __forceinline__ uint32_t smem_u32(const void* p) {
    uint32_t a;
    asm("{ .reg .u64 t; cvta.to.shared.u64 t, %1; cvt.u32.u64 %0, t; }" : "=r"(a) : "l"(p));
    return a;
}
__device__ __forceinline__ void ldsm4(uint32_t* r, const void* p) {
    uint32_t addr = smem_u32(p);
    asm volatile("ldmatrix.sync.aligned.m8n8.x4.shared.b16 {%0,%1,%2,%3}, [%4];"
        : "=r"(r[0]), "=r"(r[1]), "=r"(r[2]), "=r"(r[3]) : "r"(addr));
}
__device__ __forceinline__ void mma_bf16(float* c, const uint32_t* a, uint32_t b0, uint32_t b1) {
    asm volatile("mma.sync.aligned.m16n8k16.row.col.f32.bf16.bf16.f32 "
        "{%0,%1,%2,%3}, {%4,%5,%6,%7}, {%8,%9}, {%0,%1,%2,%3};"
        : "+f"(c[0]), "+f"(c[1]), "+f"(c[2]), "+f"(c[3])
        : "r"(a[0]), "r"(a[1]), "r"(a[2]), "r"(a[3]), "r"(b0), "r"(b1));
}

// ---------------- threefry2x32 (JAX-exact, validated by R4 pass) ----------------
__device__ __forceinline__ void threefry2x32(unsigned int x0, unsigned int x1,
                                             unsigned int& r0, unsigned int& r1) {
    const unsigned int k0 = 0u, k1 = 42u;
    const unsigned int k2 = 0u ^ 42u ^ 0x1BD11BDAu;
#define TFR(r) { x0 += x1; x1 = (x1 << (r)) | (x1 >> (32 - (r))); x1 ^= x0; }
    x0 += k0; x1 += k1;
    TFR(13) TFR(15) TFR(26) TFR(6)
    x0 += k1; x1 += k2 + 1u;
    TFR(17) TFR(29) TFR(16) TFR(24)
    x0 += k2; x1 += k0 + 2u;
    TFR(13) TFR(15) TFR(26) TFR(6)
    x0 += k0; x1 += k1 + 3u;
    TFR(17) TFR(29) TFR(16) TFR(24)
    x0 += k1; x1 += k2 + 4u;
    TFR(13) TFR(15) TFR(26) TFR(6)
    x0 += k2; x1 += k0 + 5u;
#undef TFR
    r0 = x0; r1 = x1;
}
__device__ __forceinline__ float gumbel_at(unsigned int e) {
#if JAX_PARTITIONABLE
    unsigned int r0, r1;
    threefry2x32(0u, e, r0, r1);
    unsigned int bits = r0 ^ r1;
#else
    const unsigned int NH = (NROWS * (unsigned)KCODES) / 2u;
    unsigned int p = (e < NH) ? e : (e - NH);
    unsigned int r0, r1;
    threefry2x32(p, p + NH, r0, r1);
    unsigned int bits = (e < NH) ? r0 : r1;
#endif
    float f = __uint_as_float((bits >> 9) | 0x3f800000u) - 1.0f;
    float u = fmaxf(1e-9f, f + 1e-9f);
    return -logf(-logf(u));
}

// ---------------- kernel 0: zero counts ----------------
__global__ void zero_kernel() {
    int t = threadIdx.x;
    if (t < KCODES) g_counts[t] = 0.0f;
}

// ---------------- kernel 1: transpose + bf16 big/small split ----------------
__global__ void transpose_kernel(const float* __restrict__ in) {
    __shared__ float tile[32][33];
    int b   = blockIdx.z;
    int hw0 = blockIdx.x * 32;
    int d0  = blockIdx.y * 32;
    int tx = threadIdx.x, ty = threadIdx.y;
    const float* src = in + (size_t)b * (DDIM * HWSZ);
#pragma unroll
    for (int j = 0; j < 4; j++) {
        int d  = d0 + ty + j * 8;
        int hw = hw0 + tx;
        tile[ty + j * 8][tx] = src[(size_t)d * HWSZ + hw];
    }
    __syncthreads();
#pragma unroll
    for (int j = 0; j < 4; j++) {
        int hw = hw0 + ty + j * 8;
        int d  = d0 + tx;
        float v = tile[tx][ty + j * 8];
        __nv_bfloat16 bg = __float2bfloat16(v);
        __nv_bfloat16 sm = __float2bfloat16(v - __bfloat162float(bg));
        size_t o = (size_t)(b * HWSZ + hw) * DDIM + d;
        g_Xb[o] = bg;
        g_Xs[o] = sm;
    }
}

// ---------------- kernel 2: embedding norms + bf16 split ----------------
__global__ void prep_e_kernel(const float* __restrict__ E) {
    __shared__ float red[256];
    int k = blockIdx.x, t = threadIdx.x;
    float v = E[(size_t)k * DDIM + t];
    __nv_bfloat16 bg = __float2bfloat16(v);
    __nv_bfloat16 sm = __float2bfloat16(v - __bfloat162float(bg));
    g_Eb[(size_t)k * DDIM + t] = bg;
    g_Es[(size_t)k * DDIM + t] = sm;
    red[t] = v * v;
    __syncthreads();
    for (int off = 128; off > 0; off >>= 1) {
        if (t < off) red[t] += red[t + off];
        __syncthreads();
    }
    if (t == 0) g_bnorm[k] = red[0];
}

// ---------------- kernel 3: bf16 mma.sync 3-product GEMM ----------------
// S[m][n] = 2 * x[m]·e[n] - |e[n]|^2,  x·e = Xb·Eb + Xb·Es + Xs·Eb (fp32 acc)
// BM=128, BN=128, BK=32; 8 warps, warp tile 32x64 (2 m16 x 8 n8 mma tiles)
#define LDS_ROW 40                          // bf16 elems per smem row (80B, conflict-free)
#define TILE_ELEMS (128 * LDS_ROW)
#define SMEM_DYN (512 + 2 * 4 * TILE_ELEMS * 2)   // bnorm + 2 stages x {Ab,As,Bb,Bs}

struct Pref { float4 v[8]; };

__device__ __forceinline__ void ldg_stage(Pref& p, int m0, int n0, int d0) {
    int tid = threadIdx.x;
#pragma unroll
    for (int q = 0; q < 2; q++) {
        int idx = tid + 256 * q;
        int row = idx >> 2, quad = idx & 3;
        size_t ga = (size_t)(m0 + row) * DDIM + d0 + quad * 8;
        size_t gb = (size_t)(n0 + row) * DDIM + d0 + quad * 8;
        p.v[0 * 2 + q] = *(const float4*)(g_Xb + ga);
        p.v[1 * 2 + q] = *(const float4*)(g_Xs + ga);
        p.v[2 * 2 + q] = *(const float4*)(g_Eb + gb);
        p.v[3 * 2 + q] = *(const float4*)(g_Es + gb);
    }
}

__global__ __launch_bounds__(256, 1) void gemm_bf16_kernel() {
    extern __shared__ char smem[];
    float* s_bn = (float*)smem;
    __nv_bfloat16* s_tiles = (__nv_bfloat16*)(smem + 512);
#define TILE_PTR(st, a) (s_tiles + ((st) * 4 + (a)) * TILE_ELEMS)

    int tid = threadIdx.x, wid = tid >> 5, lane = tid & 31;
    int warp_m = wid & 3, warp_n = wid >> 2;
    int n0 = blockIdx.x * 128;
    int m0 = blockIdx.y * 128;

    if (tid < 128) s_bn[tid] = g_bnorm[n0 + tid];

    float acc[2][8][4];
#pragma unroll
    for (int i = 0; i < 2; i++)
#pragma unroll
        for (int j = 0; j < 8; j++)
#pragma unroll
            for (int q = 0; q < 4; q++) acc[i][j][q] = 0.0f;

    Pref p;
    ldg_stage(p, m0, n0, 0);
    // STS stage 0
    {
#pragma unroll
        for (int q = 0; q < 2; q++) {
            int idx = tid + 256 * q;
            int row = idx >> 2, quad = idx & 3;
            int off = row * LDS_ROW + quad * 8;
#pragma unroll
            for (int a = 0; a < 4; a++)
                *(float4*)(TILE_PTR(0, a) + off) = p.v[a * 2 + q];
        }
    }
    __syncthreads();

    // per-warp ldmatrix base offsets (elems)
    int a_row = warp_m * 32 + (lane & 15);
    int b_row = warp_n * 64 + (lane & 15);
    int k_off = (lane >> 4) * 8;

    for (int c = 0; c < 8; c++) {
        if (c < 7) ldg_stage(p, m0, n0, (c + 1) * 32);
        int st = c & 1;
        const __nv_bfloat16* Ab = TILE_PTR(st, 0);
        const __nv_bfloat16* As = TILE_PTR(st, 1);
        const __nv_bfloat16* Bb = TILE_PTR(st, 2);
        const __nv_bfloat16* Bs = TILE_PTR(st, 3);
#pragma unroll
        for (int ks = 0; ks < 2; ks++) {
            int kc = ks * 16 + k_off;
            uint32_t fAb[2][4], fAs[2][4];
#pragma unroll
            for (int mt = 0; mt < 2; mt++) {
                int ro = (a_row + mt * 16) * LDS_ROW + kc;
                ldsm4(fAb[mt], Ab + ro);
                ldsm4(fAs[mt], As + ro);
            }
#pragma unroll
            for (int bt = 0; bt < 4; bt++) {
                int ro = (b_row + bt * 16) * LDS_ROW + kc;
                uint32_t fBb[4], fBs[4];
                ldsm4(fBb, Bb + ro);
                ldsm4(fBs, Bs + ro);
#pragma unroll
                for (int mi = 0; mi < 2; mi++) {
                    // n-subtile 2*bt uses regs {0,2}; 2*bt+1 uses {1,3}
                    mma_bf16(acc[mi][2 * bt],     fAb[mi], fBb[0], fBb[2]);
                    mma_bf16(acc[mi][2 * bt],     fAb[mi], fBs[0], fBs[2]);
                    mma_bf16(acc[mi][2 * bt],     fAs[mi], fBb[0], fBb[2]);
                    mma_bf16(acc[mi][2 * bt + 1], fAb[mi], fBb[1], fBb[3]);
                    mma_bf16(acc[mi][2 * bt + 1], fAb[mi], fBs[1], fBs[3]);
                    mma_bf16(acc[mi][2 * bt + 1], fAs[mi], fBb[1], fBb[3]);
                }
            }
        }
        __syncthreads();
        if (c < 7) {
            int ns = (c + 1) & 1;
#pragma unroll
            for (int q = 0; q < 2; q++) {
                int idx = tid + 256 * q;
                int row = idx >> 2, quad = idx & 3;
                int off = row * LDS_ROW + quad * 8;
#pragma unroll
                for (int a = 0; a < 4; a++)
                    *(float4*)(TILE_PTR(ns, a) + off) = p.v[a * 2 + q];
            }
            __syncthreads();
        }
    }

    // epilogue: s = 2*acc - bnorm
    int g = lane >> 2, tg = lane & 3;
#pragma unroll
    for (int mi = 0; mi < 2; mi++) {
        int r0 = m0 + warp_m * 32 + mi * 16 + g;
#pragma unroll
        for (int ni = 0; ni < 8; ni++) {
            int cl = warp_n * 64 + ni * 8 + tg * 2;
            float bn0 = s_bn[cl], bn1 = s_bn[cl + 1];
            float2 o0 = { fmaf(2.0f, acc[mi][ni][0], -bn0), fmaf(2.0f, acc[mi][ni][1], -bn1) };
            float2 o1 = { fmaf(2.0f, acc[mi][ni][2], -bn0), fmaf(2.0f, acc[mi][ni][3], -bn1) };
            *(float2*)&g_S[(size_t)r0 * KCODES + n0 + cl] = o0;
            *(float2*)&g_S[(size_t)(r0 + 8) * KCODES + n0 + cl] = o1;
        }
    }
#undef TILE_PTR
}

// ---------------- kernel 4: per-row softmax-entropy + gumbel top-2 argmax ----------------
__global__ __launch_bounds__(256)
void epi_kernel(const float* __restrict__ inp, const float* __restrict__ emb) {
    int n = blockIdx.x;
    int t = threadIdx.x;
    const float* srow = g_S + (size_t)n * KCODES;

    float4 s4 = ((const float4*)srow)[t];
    float svv[4] = {s4.x, s4.y, s4.z, s4.w};

    float v1 = NEG_INF, v2 = NEG_INF;
    int   i1 = 0x7FFFFFFF, i2 = 0x7FFFFFFF;
    float smax = NEG_INF;
#pragma unroll
    for (int jj = 0; jj < 4; jj++) {
        int k = t * 4 + jj;
        float y = svv[jj] + gumbel_at((unsigned)n * (unsigned)KCODES + (unsigned)k);
        if (y > v1 || (y == v1 && k < i1)) { v2 = v1; i2 = i1; v1 = y; i1 = k; }
        else if (y > v2 || (y == v2 && k < i2)) { v2 = y; i2 = k; }
        smax = fmaxf(smax, svv[jj]);
    }

    __shared__ float sv1[256]; __shared__ int si1[256];
    __shared__ float sv2[256]; __shared__ int si2[256];
    __shared__ float rm[256];
    __shared__ double rd1[256]; __shared__ double rd2[256];
    __shared__ int   s_bi, s_bi2;
    __shared__ float s_gap;

    sv1[t] = v1; si1[t] = i1; sv2[t] = v2; si2[t] = i2; rm[t] = smax;
    __syncthreads();
    for (int off = 128; off > 0; off >>= 1) {
        if (t < off) {
            float a1 = sv1[t];        int ai1 = si1[t];
            float a2 = sv2[t];        int ai2 = si2[t];
            float b1 = sv1[t + off];  int bi1 = si1[t + off];
            float b2 = sv2[t + off];  int bi2 = si2[t + off];
            bool bwin = (b1 > a1) || (b1 == a1 && bi1 < ai1);
            float n1, n2; int ni1, ni2;
            if (bwin) {
                n1 = b1; ni1 = bi1;
                bool aw = (a1 > b2) || (a1 == b2 && ai1 < bi2);
                n2 = aw ? a1 : b2; ni2 = aw ? ai1 : bi2;
            } else {
                n1 = a1; ni1 = ai1;
                bool bw = (b1 > a2) || (b1 == a2 && bi1 < ai2);
                n2 = bw ? b1 : a2; ni2 = bw ? bi1 : ai2;
            }
            sv1[t] = n1; si1[t] = ni1; sv2[t] = n2; si2[t] = ni2;
            rm[t] = fmaxf(rm[t], rm[t + off]);
        }
        __syncthreads();
    }
    float mrow = rm[0];
    if (t == 0) { s_bi = si1[0]; s_bi2 = si2[0]; s_gap = sv1[0] - sv2[0]; }
    __syncthreads();

    int bidx = s_bi;
    // block-parallel fp64 refinement for near ties (covers bf16-split GEMM noise)
    if (s_gap < 1e-2f) {
        int b = n >> 10, hw = n & 1023;
        float xd = inp[(size_t)b * (DDIM * HWSZ) + (size_t)t * HWSZ + hw];
        float e1 = emb[(size_t)s_bi  * DDIM + t];
        float e2 = emb[(size_t)s_bi2 * DDIM + t];
        rd1[t] = 2.0 * (double)xd * (double)e1 - (double)e1 * (double)e1;
        rd2[t] = 2.0 * (double)xd * (double)e2 - (double)e2 * (double)e2;
        __syncthreads();
        for (int off = 128; off > 0; off >>= 1) {
            if (t < off) { rd1[t] += rd1[t + off]; rd2[t] += rd2[t + off]; }
            __syncthreads();
        }
        if (t == 0) {
            double y1 = rd1[0] + (double)gumbel_at((unsigned)n * (unsigned)KCODES + (unsigned)s_bi);
            double y2 = rd2[0] + (double)gumbel_at((unsigned)n * (unsigned)KCODES + (unsigned)s_bi2);
            if (y2 > y1 || (y2 == y1 && s_bi2 < s_bi)) bidx = s_bi2;
        }
        __syncthreads();
    }

    float z = 0.0f, w = 0.0f;
#pragma unroll
    for (int jj = 0; jj < 4; jj++) {
        float d = svv[jj] - mrow;
        float e = __expf(d);
        z += e;
        w += d * e;
    }
    sv1[t] = z; rm[t] = w;
    __syncthreads();
    for (int off = 128; off > 0; off >>= 1) {
        if (t < off) { sv1[t] += sv1[t + off]; rm[t] += rm[t + off]; }
        __syncthreads();
    }
    if (t == 0) {
        float Z = sv1[0], W = rm[0];
        g_entrow[n] = W / Z - logf(Z);
        g_idx[n] = bidx;
        atomicAdd(&g_counts[bidx], 1.0f);
    }
}

// ---------------- kernel 5: scatter q_out = embedding[idx] ----------------
__global__ __launch_bounds__(256)
void scatter_kernel(const float* __restrict__ E, float* __restrict__ qout) {
    int b  = blockIdx.y;
    int hw = blockIdx.x * 256 + threadIdx.x;
    int n  = b * HWSZ + hw;
    int row = g_idx[n];
    const float4* e4 = reinterpret_cast<const float4*>(E + (size_t)row * DDIM);
    float* outb = qout + (size_t)b * (DDIM * HWSZ) + hw;
#pragma unroll 4
    for (int d4 = 0; d4 < DDIM / 4; d4++) {
        float4 v = e4[d4];
        outb[(size_t)(d4 * 4 + 0) * HWSZ] = v.x;
        outb[(size_t)(d4 * 4 + 1) * HWSZ] = v.y;
        outb[(size_t)(d4 * 4 + 2) * HWSZ] = v.z;
        outb[(size_t)(d4 * 4 + 3) * HWSZ] = v.w;
    }
}

// ---------------- kernel 6: finalize ----------------
__global__ __launch_bounds__(1024)
void finalize_kernel(float* __restrict__ out) {
    __shared__ double sh1[1024];
    __shared__ double sh2[1024];
    int t = threadIdx.x;
    double es = 0.0;
    for (int j = 0; j < NROWS / 1024; j++) es += (double)g_entrow[t + 1024 * j];
    float c = g_counts[t];
    float q = c * (1.0f / (float)NROWS);
    float term = q * logf(q + 1e-10f);
    sh1[t] = es;
    sh2[t] = (double)term;
    __syncthreads();
    for (int off = 512; off > 0; off >>= 1) {
        if (t < off) { sh1[t] += sh1[t + off]; sh2[t] += sh2[t + off]; }
        __syncthreads();
    }
    if (t == 0) {
        out[0] = 0.25f * (float)(sh1[0] / (double)NROWS);
        out[1 + QELEMS] = expf(-(float)sh2[0]);
    }
}

// ---------------- launch ----------------
extern "C" void kernel_launch(void* const* d_in, const int* in_sizes, int n_in,
                              void* d_out, int out_size) {
    const float* inp = (const float*)d_in[0];
    const float* emb = (const float*)d_in[1];
    float* out = (float*)d_out;

    cudaFuncSetAttribute(gemm_bf16_kernel, cudaFuncAttributeMaxDynamicSharedMemorySize, SMEM_DYN);

    zero_kernel<<<1, 1024>>>();
    transpose_kernel<<<dim3(HWSZ / 32, DDIM / 32, BATCH), dim3(32, 8)>>>(inp);
    prep_e_kernel<<<KCODES, 256>>>(emb);
    gemm_bf16_kernel<<<dim3(KCODES / 128, NROWS / 128), 256, SMEM_DYN>>>();
    epi_kernel<<<NROWS, 256>>>(inp, emb);
    scatter_kernel<<<dim3(HWSZ / 256, BATCH), 256>>>(emb, out + 1);
    finalize_kernel<<<1, 1024>>>(out);
}

// round 7
// speedup vs baseline: 1.6353x; 1.0172x over previous
#include <cuda_runtime.h>
#include <cuda_bf16.h>
#include <math.h>
#include <stdint.h>

// N = 64*32*32 = 65536 rows, D = 256, K = 1024
// Output layout: [loss (1), q_out (16777216), perplexity (1)]

#define NROWS   65536
#define DDIM    256
#define KCODES  1024
#define BATCH   64
#define HWSZ    1024
#define QELEMS  16777216

#define NEG_INF (-__int_as_float(0x7f800000))
#define JAX_PARTITIONABLE 1

// ---------------- scratch (device globals; no allocation allowed) ----------------
__device__ __nv_bfloat16 g_Xb[(size_t)NROWS * DDIM];   // bf16(x)         (32 MB)
__device__ __nv_bfloat16 g_Xs[(size_t)NROWS * DDIM];   // bf16(x - big)   (32 MB)
__device__ __nv_bfloat16 g_Eb[(size_t)KCODES * DDIM];
__device__ __nv_bfloat16 g_Es[(size_t)KCODES * DDIM];
__device__ float g_S[(size_t)NROWS * KCODES];          // logits          (256 MB)
__device__ float g_bnorm[KCODES];
__device__ float g_counts[KCODES];
__device__ float g_entrow[NROWS];
__device__ int   g_idx[NROWS];

// ---------------- helpers ----------------
__device__ __forceinline__ uint32_t smem_u32(const void* p) {
    uint32_t a;
    asm("{ .reg .u64 t; cvta.to.shared.u64 t, %1; cvt.u32.u64 %0, t; }" : "=r"(a) : "l"(p));
    return a;
}
__device__ __forceinline__ void ldsm4(uint32_t* r, const void* p) {
    uint32_t addr = smem_u32(p);
    asm volatile("ldmatrix.sync.aligned.m8n8.x4.shared.b16 {%0,%1,%2,%3}, [%4];"
        : "=r"(r[0]), "=r"(r[1]), "=r"(r[2]), "=r"(r[3]) : "r"(addr));
}
// NOT volatile: pure register op -> let ptxas schedule/pipeline freely
__device__ __forceinline__ void mma_bf16(float* c, const uint32_t* a, uint32_t b0, uint32_t b1) {
    asm("mma.sync.aligned.m16n8k16.row.col.f32.bf16.bf16.f32 "
        "{%0,%1,%2,%3}, {%4,%5,%6,%7}, {%8,%9}, {%0,%1,%2,%3};"
        : "+f"(c[0]), "+f"(c[1]), "+f"(c[2]), "+f"(c[3])
        : "r"(a[0]), "r"(a[1]), "r"(a[2]), "r"(a[3]), "r"(b0), "r"(b1));
}
__device__ __forceinline__ void cpa16(uint32_t s, const void* g) {
    asm volatile("cp.async.ca.shared.global [%0], [%1], 16;" :: "r"(s), "l"(g));
}
#define CPA_COMMIT() asm volatile("cp.async.commit_group;" ::: "memory")
#define CPA_WAIT1()  asm volatile("cp.async.wait_group 1;" ::: "memory")

// ---------------- threefry2x32 (JAX-exact, validated by R4/R6 passes) ----------------
__device__ __forceinline__ void threefry2x32(unsigned int x0, unsigned int x1,
                                             unsigned int& r0, unsigned int& r1) {
    const unsigned int k0 = 0u, k1 = 42u;
    const unsigned int k2 = 0u ^ 42u ^ 0x1BD11BDAu;
#define TFR(r) { x0 += x1; x1 = (x1 << (r)) | (x1 >> (32 - (r))); x1 ^= x0; }
    x0 += k0; x1 += k1;
    TFR(13) TFR(15) TFR(26) TFR(6)
    x0 += k1; x1 += k2 + 1u;
    TFR(17) TFR(29) TFR(16) TFR(24)
    x0 += k2; x1 += k0 + 2u;
    TFR(13) TFR(15) TFR(26) TFR(6)
    x0 += k0; x1 += k1 + 3u;
    TFR(17) TFR(29) TFR(16) TFR(24)
    x0 += k1; x1 += k2 + 4u;
    TFR(13) TFR(15) TFR(26) TFR(6)
    x0 += k2; x1 += k0 + 5u;
#undef TFR
    r0 = x0; r1 = x1;
}
__device__ __forceinline__ float gumbel_at(unsigned int e) {
#if JAX_PARTITIONABLE
    unsigned int r0, r1;
    threefry2x32(0u, e, r0, r1);
    unsigned int bits = r0 ^ r1;
#else
    const unsigned int NH = (NROWS * (unsigned)KCODES) / 2u;
    unsigned int p = (e < NH) ? e : (e - NH);
    unsigned int r0, r1;
    threefry2x32(p, p + NH, r0, r1);
    unsigned int bits = (e < NH) ? r0 : r1;
#endif
    float f = __uint_as_float((bits >> 9) | 0x3f800000u) - 1.0f;
    float u = fmaxf(1e-9f, f + 1e-9f);
    return -logf(-logf(u));
}

// ---------------- kernel 0: zero counts ----------------
__global__ void zero_kernel() {
    int t = threadIdx.x;
    if (t < KCODES) g_counts[t] = 0.0f;
}

// ---------------- kernel 1: transpose + bf16 big/small split ----------------
__global__ void transpose_kernel(const float* __restrict__ in) {
    __shared__ float tile[32][33];
    int b   = blockIdx.z;
    int hw0 = blockIdx.x * 32;
    int d0  = blockIdx.y * 32;
    int tx = threadIdx.x, ty = threadIdx.y;
    const float* src = in + (size_t)b * (DDIM * HWSZ);
#pragma unroll
    for (int j = 0; j < 4; j++) {
        int d  = d0 + ty + j * 8;
        int hw = hw0 + tx;
        tile[ty + j * 8][tx] = src[(size_t)d * HWSZ + hw];
    }
    __syncthreads();
#pragma unroll
    for (int j = 0; j < 4; j++) {
        int hw = hw0 + ty + j * 8;
        int d  = d0 + tx;
        float v = tile[tx][ty + j * 8];
        __nv_bfloat16 bg = __float2bfloat16(v);
        __nv_bfloat16 sm = __float2bfloat16(v - __bfloat162float(bg));
        size_t o = (size_t)(b * HWSZ + hw) * DDIM + d;
        g_Xb[o] = bg;
        g_Xs[o] = sm;
    }
}

// ---------------- kernel 2: embedding norms + bf16 split ----------------
__global__ void prep_e_kernel(const float* __restrict__ E) {
    __shared__ float red[256];
    int k = blockIdx.x, t = threadIdx.x;
    float v = E[(size_t)k * DDIM + t];
    __nv_bfloat16 bg = __float2bfloat16(v);
    __nv_bfloat16 sm = __float2bfloat16(v - __bfloat162float(bg));
    g_Eb[(size_t)k * DDIM + t] = bg;
    g_Es[(size_t)k * DDIM + t] = sm;
    red[t] = v * v;
    __syncthreads();
    for (int off = 128; off > 0; off >>= 1) {
        if (t < off) red[t] += red[t + off];
        __syncthreads();
    }
    if (t == 0) g_bnorm[k] = red[0];
}

// ---------------- kernel 3: bf16 mma.sync 3-product GEMM, cp.async 3-stage ----------------
// S[m][n] = 2 * x[m]·e[n] - |e[n]|^2,  x·e = Xb·Eb + Xb·Es + Xs·Eb (fp32 acc)
// BM=128, BN=128, BK=32; 8 warps, warp tile 32x64
#define LDS_ROW 40                                  // bf16 elems per smem row (80B)
#define TILE_ELEMS (128 * LDS_ROW)
#define TILE_BYTES (TILE_ELEMS * 2)                 // 10240
#define NSTAGE 3
#define SMEM_DYN (512 + NSTAGE * 4 * TILE_BYTES)    // 512 + 122880 = 123392

__device__ __forceinline__ void issue_stage(uint32_t s_tiles_u32, int buf, int m0, int n0, int d0) {
    int tid = threadIdx.x;
    uint32_t base = s_tiles_u32 + (uint32_t)buf * 4 * TILE_BYTES;
#pragma unroll
    for (int q = 0; q < 2; q++) {
        int idx = tid + 256 * q;
        int row = idx >> 2, quad = idx & 3;
        uint32_t soff = (uint32_t)(row * LDS_ROW + quad * 8) * 2;
        size_t ga = (size_t)(m0 + row) * DDIM + d0 + quad * 8;
        size_t gb = (size_t)(n0 + row) * DDIM + d0 + quad * 8;
        cpa16(base + 0 * TILE_BYTES + soff, g_Xb + ga);
        cpa16(base + 1 * TILE_BYTES + soff, g_Xs + ga);
        cpa16(base + 2 * TILE_BYTES + soff, g_Eb + gb);
        cpa16(base + 3 * TILE_BYTES + soff, g_Es + gb);
    }
}

__global__ __launch_bounds__(256, 1) void gemm_bf16_kernel() {
    extern __shared__ char smem[];
    float* s_bn = (float*)smem;
    __nv_bfloat16* s_tiles = (__nv_bfloat16*)(smem + 512);
    uint32_t s_tiles_u32 = smem_u32(s_tiles);
#define TILE_PTR(st, a) (s_tiles + ((st) * 4 + (a)) * TILE_ELEMS)

    int tid = threadIdx.x, wid = tid >> 5, lane = tid & 31;
    int warp_m = wid & 3, warp_n = wid >> 2;
    int n0 = blockIdx.x * 128;
    int m0 = blockIdx.y * 128;

    if (tid < 128) s_bn[tid] = g_bnorm[n0 + tid];

    float acc[2][8][4];
#pragma unroll
    for (int i = 0; i < 2; i++)
#pragma unroll
        for (int j = 0; j < 8; j++)
#pragma unroll
            for (int q = 0; q < 4; q++) acc[i][j][q] = 0.0f;

    // prologue: stages 0 and 1 in flight
    issue_stage(s_tiles_u32, 0, m0, n0, 0);
    CPA_COMMIT();
    issue_stage(s_tiles_u32, 1, m0, n0, 32);
    CPA_COMMIT();

    // per-warp ldmatrix base offsets (elems)
    int a_row = warp_m * 32 + (lane & 15);
    int b_row = warp_n * 64 + (lane & 15);
    int k_off = (lane >> 4) * 8;

    for (int c = 0; c < 8; c++) {
        CPA_WAIT1();           // stage c landed (stage c+1 may still fly)
        __syncthreads();       // all warps see stage c; all done reading buf (c+2)%3
        if (c + 2 < 8) {
            issue_stage(s_tiles_u32, (c + 2) % NSTAGE, m0, n0, (c + 2) * 32);
            CPA_COMMIT();
        }
        int st = c % NSTAGE;
        const __nv_bfloat16* Ab = TILE_PTR(st, 0);
        const __nv_bfloat16* As = TILE_PTR(st, 1);
        const __nv_bfloat16* Bb = TILE_PTR(st, 2);
        const __nv_bfloat16* Bs = TILE_PTR(st, 3);
#pragma unroll
        for (int ks = 0; ks < 2; ks++) {
            int kc = ks * 16 + k_off;
            uint32_t fAb[2][4], fAs[2][4];
#pragma unroll
            for (int mt = 0; mt < 2; mt++) {
                int ro = (a_row + mt * 16) * LDS_ROW + kc;
                ldsm4(fAb[mt], Ab + ro);
                ldsm4(fAs[mt], As + ro);
            }
#pragma unroll
            for (int bt = 0; bt < 4; bt++) {
                int ro = (b_row + bt * 16) * LDS_ROW + kc;
                uint32_t fBb[4], fBs[4];
                ldsm4(fBb, Bb + ro);
                ldsm4(fBs, Bs + ro);
                float* c00 = acc[0][2 * bt];
                float* c10 = acc[1][2 * bt];
                float* c01 = acc[0][2 * bt + 1];
                float* c11 = acc[1][2 * bt + 1];
                // round-robin across 4 independent accumulators: RAW distance 4
                mma_bf16(c00, fAb[0], fBb[0], fBb[2]);
                mma_bf16(c10, fAb[1], fBb[0], fBb[2]);
                mma_bf16(c01, fAb[0], fBb[1], fBb[3]);
                mma_bf16(c11, fAb[1], fBb[1], fBb[3]);
                mma_bf16(c00, fAb[0], fBs[0], fBs[2]);
                mma_bf16(c10, fAb[1], fBs[0], fBs[2]);
                mma_bf16(c01, fAb[0], fBs[1], fBs[3]);
                mma_bf16(c11, fAb[1], fBs[1], fBs[3]);
                mma_bf16(c00, fAs[0], fBb[0], fBb[2]);
                mma_bf16(c10, fAs[1], fBb[0], fBb[2]);
                mma_bf16(c01, fAs[0], fBb[1], fBb[3]);
                mma_bf16(c11, fAs[1], fBb[1], fBb[3]);
            }
        }
    }

    // epilogue: s = 2*acc - bnorm
    int g = lane >> 2, tg = lane & 3;
#pragma unroll
    for (int mi = 0; mi < 2; mi++) {
        int r0 = m0 + warp_m * 32 + mi * 16 + g;
#pragma unroll
        for (int ni = 0; ni < 8; ni++) {
            int cl = warp_n * 64 + ni * 8 + tg * 2;
            float bn0 = s_bn[cl], bn1 = s_bn[cl + 1];
            float2 o0 = { fmaf(2.0f, acc[mi][ni][0], -bn0), fmaf(2.0f, acc[mi][ni][1], -bn1) };
            float2 o1 = { fmaf(2.0f, acc[mi][ni][2], -bn0), fmaf(2.0f, acc[mi][ni][3], -bn1) };
            *(float2*)&g_S[(size_t)r0 * KCODES + n0 + cl] = o0;
            *(float2*)&g_S[(size_t)(r0 + 8) * KCODES + n0 + cl] = o1;
        }
    }
#undef TILE_PTR
}

// ---------------- kernel 4: per-row softmax-entropy + gumbel top-2 argmax ----------------
__global__ __launch_bounds__(256)
void epi_kernel(const float* __restrict__ inp, const float* __restrict__ emb) {
    int n = blockIdx.x;
    int t = threadIdx.x;
    const float* srow = g_S + (size_t)n * KCODES;

    float4 s4 = ((const float4*)srow)[t];
    float svv[4] = {s4.x, s4.y, s4.z, s4.w};

    float v1 = NEG_INF, v2 = NEG_INF;
    int   i1 = 0x7FFFFFFF, i2 = 0x7FFFFFFF;
    float smax = NEG_INF;
#pragma unroll
    for (int jj = 0; jj < 4; jj++) {
        int k = t * 4 + jj;
        float y = svv[jj] + gumbel_at((unsigned)n * (unsigned)KCODES + (unsigned)k);
        if (y > v1 || (y == v1 && k < i1)) { v2 = v1; i2 = i1; v1 = y; i1 = k; }
        else if (y > v2 || (y == v2 && k < i2)) { v2 = y; i2 = k; }
        smax = fmaxf(smax, svv[jj]);
    }

    __shared__ float sv1[256]; __shared__ int si1[256];
    __shared__ float sv2[256]; __shared__ int si2[256];
    __shared__ float rm[256];
    __shared__ double rd1[256]; __shared__ double rd2[256];
    __shared__ int   s_bi, s_bi2;
    __shared__ float s_gap;

    sv1[t] = v1; si1[t] = i1; sv2[t] = v2; si2[t] = i2; rm[t] = smax;
    __syncthreads();
    for (int off = 128; off > 0; off >>= 1) {
        if (t < off) {
            float a1 = sv1[t];        int ai1 = si1[t];
            float a2 = sv2[t];        int ai2 = si2[t];
            float b1 = sv1[t + off];  int bi1 = si1[t + off];
            float b2 = sv2[t + off];  int bi2 = si2[t + off];
            bool bwin = (b1 > a1) || (b1 == a1 && bi1 < ai1);
            float n1, n2; int ni1, ni2;
            if (bwin) {
                n1 = b1; ni1 = bi1;
                bool aw = (a1 > b2) || (a1 == b2 && ai1 < bi2);
                n2 = aw ? a1 : b2; ni2 = aw ? ai1 : bi2;
            } else {
                n1 = a1; ni1 = ai1;
                bool bw = (b1 > a2) || (b1 == a2 && bi1 < ai2);
                n2 = bw ? b1 : a2; ni2 = bw ? bi1 : ai2;
            }
            sv1[t] = n1; si1[t] = ni1; sv2[t] = n2; si2[t] = ni2;
            rm[t] = fmaxf(rm[t], rm[t + off]);
        }
        __syncthreads();
    }
    float mrow = rm[0];
    if (t == 0) { s_bi = si1[0]; s_bi2 = si2[0]; s_gap = sv1[0] - sv2[0]; }
    __syncthreads();

    int bidx = s_bi;
    // block-parallel fp64 refinement for near ties (covers bf16-split GEMM noise)
    if (s_gap < 1e-2f) {
        int b = n >> 10, hw = n & 1023;
        float xd = inp[(size_t)b * (DDIM * HWSZ) + (size_t)t * HWSZ + hw];
        float e1 = emb[(size_t)s_bi  * DDIM + t];
        float e2 = emb[(size_t)s_bi2 * DDIM + t];
        rd1[t] = 2.0 * (double)xd * (double)e1 - (double)e1 * (double)e1;
        rd2[t] = 2.0 * (double)xd * (double)e2 - (double)e2 * (double)e2;
        __syncthreads();
        for (int off = 128; off > 0; off >>= 1) {
            if (t < off) { rd1[t] += rd1[t + off]; rd2[t] += rd2[t + off]; }
            __syncthreads();
        }
        if (t == 0) {
            double y1 = rd1[0] + (double)gumbel_at((unsigned)n * (unsigned)KCODES + (unsigned)s_bi);
            double y2 = rd2[0] + (double)gumbel_at((unsigned)n * (unsigned)KCODES + (unsigned)s_bi2);
            if (y2 > y1 || (y2 == y1 && s_bi2 < s_bi)) bidx = s_bi2;
        }
        __syncthreads();
    }

    float z = 0.0f, w = 0.0f;
#pragma unroll
    for (int jj = 0; jj < 4; jj++) {
        float d = svv[jj] - mrow;
        float e = __expf(d);
        z += e;
        w += d * e;
    }
    sv1[t] = z; rm[t] = w;
    __syncthreads();
    for (int off = 128; off > 0; off >>= 1) {
        if (t < off) { sv1[t] += sv1[t + off]; rm[t] += rm[t + off]; }
        __syncthreads();
    }
    if (t == 0) {
        float Z = sv1[0], W = rm[0];
        g_entrow[n] = W / Z - logf(Z);
        g_idx[n] = bidx;
        atomicAdd(&g_counts[bidx], 1.0f);
    }
}

// ---------------- kernel 5: scatter q_out = embedding[idx] ----------------
__global__ __launch_bounds__(256)
void scatter_kernel(const float* __restrict__ E, float* __restrict__ qout) {
    int b  = blockIdx.y;
    int hw = blockIdx.x * 256 + threadIdx.x;
    int n  = b * HWSZ + hw;
    int row = g_idx[n];
    const float4* e4 = reinterpret_cast<const float4*>(E + (size_t)row * DDIM);
    float* outb = qout + (size_t)b * (DDIM * HWSZ) + hw;
#pragma unroll 4
    for (int d4 = 0; d4 < DDIM / 4; d4++) {
        float4 v = e4[d4];
        outb[(size_t)(d4 * 4 + 0) * HWSZ] = v.x;
        outb[(size_t)(d4 * 4 + 1) * HWSZ] = v.y;
        outb[(size_t)(d4 * 4 + 2) * HWSZ] = v.z;
        outb[(size_t)(d4 * 4 + 3) * HWSZ] = v.w;
    }
}

// ---------------- kernel 6: finalize ----------------
__global__ __launch_bounds__(1024)
void finalize_kernel(float* __restrict__ out) {
    __shared__ double sh1[1024];
    __shared__ double sh2[1024];
    int t = threadIdx.x;
    double es = 0.0;
    for (int j = 0; j < NROWS / 1024; j++) es += (double)g_entrow[t + 1024 * j];
    float c = g_counts[t];
    float q = c * (1.0f / (float)NROWS);
    float term = q * logf(q + 1e-10f);
    sh1[t] = es;
    sh2[t] = (double)term;
    __syncthreads();
    for (int off = 512; off > 0; off >>= 1) {
        if (t < off) { sh1[t] += sh1[t + off]; sh2[t] += sh2[t + off]; }
        __syncthreads();
    }
    if (t == 0) {
        out[0] = 0.25f * (float)(sh1[0] / (double)NROWS);
        out[1 + QELEMS] = expf(-(float)sh2[0]);
    }
}

// ---------------- launch ----------------
extern "C" void kernel_launch(void* const* d_in, const int* in_sizes, int n_in,
                              void* d_out, int out_size) {
    const float* inp = (const float*)d_in[0];
    const float* emb = (const float*)d_in[1];
    float* out = (float*)d_out;

    cudaFuncSetAttribute(gemm_bf16_kernel, cudaFuncAttributeMaxDynamicSharedMemorySize, SMEM_DYN);

    zero_kernel<<<1, 1024>>>();
    transpose_kernel<<<dim3(HWSZ / 32, DDIM / 32, BATCH), dim3(32, 8)>>>(inp);
    prep_e_kernel<<<KCODES, 256>>>(emb);
    gemm_bf16_kernel<<<dim3(KCODES / 128, NROWS / 128), 256, SMEM_DYN>>>();
    epi_kernel<<<NROWS, 256>>>(inp, emb);
    scatter_kernel<<<dim3(HWSZ / 256, BATCH), 256>>>(emb, out + 1);
    finalize_kernel<<<1, 1024>>>(out);
}

// round 8
// speedup vs baseline: 2.2901x; 1.4004x over previous
#include <cuda_runtime.h>
#include <cuda_fp16.h>
#include <math.h>
#include <stdint.h>

// N = 64*32*32 = 65536 rows, D = 256, K = 1024
// Output layout: [loss (1), q_out (16777216), perplexity (1)]

#define NROWS   65536
#define DDIM    256
#define KCODES  1024
#define BATCH   64
#define HWSZ    1024
#define QELEMS  16777216

#define NEG_INF (-__int_as_float(0x7f800000))
#define JAX_PARTITIONABLE 1

// ---------------- scratch (device globals; no allocation allowed) ----------------
__device__ __half g_Xh[(size_t)NROWS * DDIM];          // fp16(x)         (32 MB)
__device__ __half g_Eh[(size_t)KCODES * DDIM];         // fp16(e)
__device__ float g_S[(size_t)NROWS * KCODES];          // logits          (256 MB)
__device__ float g_bnorm[KCODES];
__device__ float g_counts[KCODES];
__device__ float g_entrow[NROWS];
__device__ int   g_idx[NROWS];

// ---------------- helpers ----------------
__device__ __forceinline__ uint32_t smem_u32(const void* p) {
    uint32_t a;
    asm("{ .reg .u64 t; cvta.to.shared.u64 t, %1; cvt.u32.u64 %0, t; }" : "=r"(a) : "l"(p));
    return a;
}
__device__ __forceinline__ void ldsm4(uint32_t* r, const void* p) {
    uint32_t addr = smem_u32(p);
    asm volatile("ldmatrix.sync.aligned.m8n8.x4.shared.b16 {%0,%1,%2,%3}, [%4];"
        : "=r"(r[0]), "=r"(r[1]), "=r"(r[2]), "=r"(r[3]) : "r"(addr));
}
// NOT volatile: pure register op -> let ptxas schedule freely
__device__ __forceinline__ void mma_f16(float* c, const uint32_t* a, uint32_t b0, uint32_t b1) {
    asm("mma.sync.aligned.m16n8k16.row.col.f32.f16.f16.f32 "
        "{%0,%1,%2,%3}, {%4,%5,%6,%7}, {%8,%9}, {%0,%1,%2,%3};"
        : "+f"(c[0]), "+f"(c[1]), "+f"(c[2]), "+f"(c[3])
        : "r"(a[0]), "r"(a[1]), "r"(a[2]), "r"(a[3]), "r"(b0), "r"(b1));
}
__device__ __forceinline__ void cpa16(uint32_t s, const void* g) {
    asm volatile("cp.async.ca.shared.global [%0], [%1], 16;" :: "r"(s), "l"(g));
}
#define CPA_COMMIT() asm volatile("cp.async.commit_group;" ::: "memory")
#define CPA_WAIT1()  asm volatile("cp.async.wait_group 1;" ::: "memory")

// ---------------- threefry2x32 (JAX-exact, validated R4/R6/R7) ----------------
__device__ __forceinline__ void threefry2x32(unsigned int x0, unsigned int x1,
                                             unsigned int& r0, unsigned int& r1) {
    const unsigned int k0 = 0u, k1 = 42u;
    const unsigned int k2 = 0u ^ 42u ^ 0x1BD11BDAu;
#define TFR(r) { x0 += x1; x1 = (x1 << (r)) | (x1 >> (32 - (r))); x1 ^= x0; }
    x0 += k0; x1 += k1;
    TFR(13) TFR(15) TFR(26) TFR(6)
    x0 += k1; x1 += k2 + 1u;
    TFR(17) TFR(29) TFR(16) TFR(24)
    x0 += k2; x1 += k0 + 2u;
    TFR(13) TFR(15) TFR(26) TFR(6)
    x0 += k0; x1 += k1 + 3u;
    TFR(17) TFR(29) TFR(16) TFR(24)
    x0 += k1; x1 += k2 + 4u;
    TFR(13) TFR(15) TFR(26) TFR(6)
    x0 += k2; x1 += k0 + 5u;
#undef TFR
    r0 = x0; r1 = x1;
}
__device__ __forceinline__ float gumbel_at(unsigned int e) {
#if JAX_PARTITIONABLE
    unsigned int r0, r1;
    threefry2x32(0u, e, r0, r1);
    unsigned int bits = r0 ^ r1;
#else
    const unsigned int NH = (NROWS * (unsigned)KCODES) / 2u;
    unsigned int p = (e < NH) ? e : (e - NH);
    unsigned int r0, r1;
    threefry2x32(p, p + NH, r0, r1);
    unsigned int bits = (e < NH) ? r0 : r1;
#endif
    float f = __uint_as_float((bits >> 9) | 0x3f800000u) - 1.0f;
    float u = fmaxf(1e-9f, f + 1e-9f);
    return -logf(-logf(u));
}

// ---------------- kernel 0: zero counts ----------------
__global__ void zero_kernel() {
    int t = threadIdx.x;
    if (t < KCODES) g_counts[t] = 0.0f;
}

// ---------------- kernel 1: transpose + fp16 convert ----------------
__global__ void transpose_kernel(const float* __restrict__ in) {
    __shared__ float tile[32][33];
    int b   = blockIdx.z;
    int hw0 = blockIdx.x * 32;
    int d0  = blockIdx.y * 32;
    int tx = threadIdx.x, ty = threadIdx.y;
    const float* src = in + (size_t)b * (DDIM * HWSZ);
#pragma unroll
    for (int j = 0; j < 4; j++) {
        int d  = d0 + ty + j * 8;
        int hw = hw0 + tx;
        tile[ty + j * 8][tx] = src[(size_t)d * HWSZ + hw];
    }
    __syncthreads();
#pragma unroll
    for (int j = 0; j < 4; j++) {
        int hw = hw0 + ty + j * 8;
        int d  = d0 + tx;
        g_Xh[(size_t)(b * HWSZ + hw) * DDIM + d] = __float2half_rn(tile[tx][ty + j * 8]);
    }
}

// ---------------- kernel 2: embedding norms + fp16 convert ----------------
__global__ void prep_e_kernel(const float* __restrict__ E) {
    __shared__ float red[256];
    int k = blockIdx.x, t = threadIdx.x;
    float v = E[(size_t)k * DDIM + t];
    g_Eh[(size_t)k * DDIM + t] = __float2half_rn(v);
    red[t] = v * v;
    __syncthreads();
    for (int off = 128; off > 0; off >>= 1) {
        if (t < off) red[t] += red[t + off];
        __syncthreads();
    }
    if (t == 0) g_bnorm[k] = red[0];
}

// ---------------- kernel 3: fp16 mma.sync GEMM, cp.async 3-stage, 2 CTA/SM ----------------
// S[m][n] = 2 * x[m]·e[n] - |e[n]|^2  (single fp16 product, fp32 accumulate)
// BM=128, BN=128, BK=32; 8 warps, warp tile 32x64
#define LDS_ROW 40                                  // fp16 elems per smem row (80B)
#define TILE_ELEMS (128 * LDS_ROW)
#define TILE_BYTES (TILE_ELEMS * 2)                 // 10240
#define NSTAGE 3
#define SMEM_DYN (512 + NSTAGE * 2 * TILE_BYTES)    // 512 + 61440 = 61952

__device__ __forceinline__ void issue_stage(uint32_t s_tiles_u32, int buf, int m0, int n0, int d0) {
    int tid = threadIdx.x;
    uint32_t base = s_tiles_u32 + (uint32_t)buf * 2 * TILE_BYTES;
#pragma unroll
    for (int q = 0; q < 2; q++) {
        int idx = tid + 256 * q;
        int row = idx >> 2, quad = idx & 3;
        uint32_t soff = (uint32_t)(row * LDS_ROW + quad * 8) * 2;
        size_t ga = (size_t)(m0 + row) * DDIM + d0 + quad * 8;
        size_t gb = (size_t)(n0 + row) * DDIM + d0 + quad * 8;
        cpa16(base + 0 * TILE_BYTES + soff, g_Xh + ga);
        cpa16(base + 1 * TILE_BYTES + soff, g_Eh + gb);
    }
}

__global__ __launch_bounds__(256, 2) void gemm_f16_kernel() {
    extern __shared__ char smem[];
    float* s_bn = (float*)smem;
    __half* s_tiles = (__half*)(smem + 512);
    uint32_t s_tiles_u32 = smem_u32(s_tiles);
#define TILE_PTR(st, a) (s_tiles + ((st) * 2 + (a)) * TILE_ELEMS)

    int tid = threadIdx.x, wid = tid >> 5, lane = tid & 31;
    int warp_m = wid & 3, warp_n = wid >> 2;
    int n0 = blockIdx.x * 128;
    int m0 = blockIdx.y * 128;

    if (tid < 128) s_bn[tid] = g_bnorm[n0 + tid];

    float acc[2][8][4];
#pragma unroll
    for (int i = 0; i < 2; i++)
#pragma unroll
        for (int j = 0; j < 8; j++)
#pragma unroll
            for (int q = 0; q < 4; q++) acc[i][j][q] = 0.0f;

    issue_stage(s_tiles_u32, 0, m0, n0, 0);
    CPA_COMMIT();
    issue_stage(s_tiles_u32, 1, m0, n0, 32);
    CPA_COMMIT();

    int a_row = warp_m * 32 + (lane & 15);
    int b_row = warp_n * 64 + (lane & 15);
    int k_off = (lane >> 4) * 8;

    for (int c = 0; c < 8; c++) {
        CPA_WAIT1();           // stage c landed
        __syncthreads();       // all warps done reading buf (c+2)%3
        if (c + 2 < 8) {
            issue_stage(s_tiles_u32, (c + 2) % NSTAGE, m0, n0, (c + 2) * 32);
            CPA_COMMIT();
        }
        int st = c % NSTAGE;
        const __half* At = TILE_PTR(st, 0);
        const __half* Bt = TILE_PTR(st, 1);
#pragma unroll
        for (int ks = 0; ks < 2; ks++) {
            int kc = ks * 16 + k_off;
            uint32_t fA[2][4];
#pragma unroll
            for (int mt = 0; mt < 2; mt++)
                ldsm4(fA[mt], At + (a_row + mt * 16) * LDS_ROW + kc);
#pragma unroll
            for (int bt = 0; bt < 4; bt++) {
                uint32_t fB[4];
                ldsm4(fB, Bt + (b_row + bt * 16) * LDS_ROW + kc);
                // round-robin across 4 independent accumulators
                mma_f16(acc[0][2 * bt],     fA[0], fB[0], fB[2]);
                mma_f16(acc[1][2 * bt],     fA[1], fB[0], fB[2]);
                mma_f16(acc[0][2 * bt + 1], fA[0], fB[1], fB[3]);
                mma_f16(acc[1][2 * bt + 1], fA[1], fB[1], fB[3]);
            }
        }
    }

    // epilogue: s = 2*acc - bnorm
    int g = lane >> 2, tg = lane & 3;
#pragma unroll
    for (int mi = 0; mi < 2; mi++) {
        int r0 = m0 + warp_m * 32 + mi * 16 + g;
#pragma unroll
        for (int ni = 0; ni < 8; ni++) {
            int cl = warp_n * 64 + ni * 8 + tg * 2;
            float bn0 = s_bn[cl], bn1 = s_bn[cl + 1];
            float2 o0 = { fmaf(2.0f, acc[mi][ni][0], -bn0), fmaf(2.0f, acc[mi][ni][1], -bn1) };
            float2 o1 = { fmaf(2.0f, acc[mi][ni][2], -bn0), fmaf(2.0f, acc[mi][ni][3], -bn1) };
            *(float2*)&g_S[(size_t)r0 * KCODES + n0 + cl] = o0;
            *(float2*)&g_S[(size_t)(r0 + 8) * KCODES + n0 + cl] = o1;
        }
    }
#undef TILE_PTR
}

// ---------------- kernel 4: per-row softmax-entropy + gumbel top-2 argmax ----------------
__global__ __launch_bounds__(256)
void epi_kernel(const float* __restrict__ inp, const float* __restrict__ emb) {
    int n = blockIdx.x;
    int t = threadIdx.x;
    const float* srow = g_S + (size_t)n * KCODES;

    float4 s4 = ((const float4*)srow)[t];
    float svv[4] = {s4.x, s4.y, s4.z, s4.w};

    float v1 = NEG_INF, v2 = NEG_INF;
    int   i1 = 0x7FFFFFFF, i2 = 0x7FFFFFFF;
    float smax = NEG_INF;
#pragma unroll
    for (int jj = 0; jj < 4; jj++) {
        int k = t * 4 + jj;
        float y = svv[jj] + gumbel_at((unsigned)n * (unsigned)KCODES + (unsigned)k);
        if (y > v1 || (y == v1 && k < i1)) { v2 = v1; i2 = i1; v1 = y; i1 = k; }
        else if (y > v2 || (y == v2 && k < i2)) { v2 = y; i2 = k; }
        smax = fmaxf(smax, svv[jj]);
    }

    __shared__ float sv1[256]; __shared__ int si1[256];
    __shared__ float sv2[256]; __shared__ int si2[256];
    __shared__ float rm[256];
    __shared__ double rd1[256]; __shared__ double rd2[256];
    __shared__ int   s_bi, s_bi2;
    __shared__ float s_gap;

    sv1[t] = v1; si1[t] = i1; sv2[t] = v2; si2[t] = i2; rm[t] = smax;
    __syncthreads();
    for (int off = 128; off > 0; off >>= 1) {
        if (t < off) {
            float a1 = sv1[t];        int ai1 = si1[t];
            float a2 = sv2[t];        int ai2 = si2[t];
            float b1 = sv1[t + off];  int bi1 = si1[t + off];
            float b2 = sv2[t + off];  int bi2 = si2[t + off];
            bool bwin = (b1 > a1) || (b1 == a1 && bi1 < ai1);
            float n1, n2; int ni1, ni2;
            if (bwin) {
                n1 = b1; ni1 = bi1;
                bool aw = (a1 > b2) || (a1 == b2 && ai1 < bi2);
                n2 = aw ? a1 : b2; ni2 = aw ? ai1 : bi2;
            } else {
                n1 = a1; ni1 = ai1;
                bool bw = (b1 > a2) || (b1 == a2 && bi1 < ai2);
                n2 = bw ? b1 : a2; ni2 = bw ? bi1 : ai2;
            }
            sv1[t] = n1; si1[t] = ni1; sv2[t] = n2; si2[t] = ni2;
            rm[t] = fmaxf(rm[t], rm[t + off]);
        }
        __syncthreads();
    }
    float mrow = rm[0];
    if (t == 0) { s_bi = si1[0]; s_bi2 = si2[0]; s_gap = sv1[0] - sv2[0]; }
    __syncthreads();

    int bidx = s_bi;
    // block-parallel fp64 refinement for near ties (covers fp16 GEMM noise)
    if (s_gap < 1e-2f) {
        int b = n >> 10, hw = n & 1023;
        float xd = inp[(size_t)b * (DDIM * HWSZ) + (size_t)t * HWSZ + hw];
        float e1 = emb[(size_t)s_bi  * DDIM + t];
        float e2 = emb[(size_t)s_bi2 * DDIM + t];
        rd1[t] = 2.0 * (double)xd * (double)e1 - (double)e1 * (double)e1;
        rd2[t] = 2.0 * (double)xd * (double)e2 - (double)e2 * (double)e2;
        __syncthreads();
        for (int off = 128; off > 0; off >>= 1) {
            if (t < off) { rd1[t] += rd1[t + off]; rd2[t] += rd2[t + off]; }
            __syncthreads();
        }
        if (t == 0) {
            double y1 = rd1[0] + (double)gumbel_at((unsigned)n * (unsigned)KCODES + (unsigned)s_bi);
            double y2 = rd2[0] + (double)gumbel_at((unsigned)n * (unsigned)KCODES + (unsigned)s_bi2);
            if (y2 > y1 || (y2 == y1 && s_bi2 < s_bi)) bidx = s_bi2;
        }
        __syncthreads();
    }

    float z = 0.0f, w = 0.0f;
#pragma unroll
    for (int jj = 0; jj < 4; jj++) {
        float d = svv[jj] - mrow;
        float e = __expf(d);
        z += e;
        w += d * e;
    }
    sv1[t] = z; rm[t] = w;
    __syncthreads();
    for (int off = 128; off > 0; off >>= 1) {
        if (t < off) { sv1[t] += sv1[t + off]; rm[t] += rm[t + off]; }
        __syncthreads();
    }
    if (t == 0) {
        float Z = sv1[0], W = rm[0];
        g_entrow[n] = W / Z - logf(Z);
        g_idx[n] = bidx;
        atomicAdd(&g_counts[bidx], 1.0f);
    }
}

// ---------------- kernel 5: scatter q_out = embedding[idx] ----------------
__global__ __launch_bounds__(256)
void scatter_kernel(const float* __restrict__ E, float* __restrict__ qout) {
    int b  = blockIdx.y;
    int hw = blockIdx.x * 256 + threadIdx.x;
    int n  = b * HWSZ + hw;
    int row = g_idx[n];
    const float4* e4 = reinterpret_cast<const float4*>(E + (size_t)row * DDIM);
    float* outb = qout + (size_t)b * (DDIM * HWSZ) + hw;
#pragma unroll 4
    for (int d4 = 0; d4 < DDIM / 4; d4++) {
        float4 v = e4[d4];
        outb[(size_t)(d4 * 4 + 0) * HWSZ] = v.x;
        outb[(size_t)(d4 * 4 + 1) * HWSZ] = v.y;
        outb[(size_t)(d4 * 4 + 2) * HWSZ] = v.z;
        outb[(size_t)(d4 * 4 + 3) * HWSZ] = v.w;
    }
}

// ---------------- kernel 6: finalize ----------------
__global__ __launch_bounds__(1024)
void finalize_kernel(float* __restrict__ out) {
    __shared__ double sh1[1024];
    __shared__ double sh2[1024];
    int t = threadIdx.x;
    double es = 0.0;
    for (int j = 0; j < NROWS / 1024; j++) es += (double)g_entrow[t + 1024 * j];
    float c = g_counts[t];
    float q = c * (1.0f / (float)NROWS);
    float term = q * logf(q + 1e-10f);
    sh1[t] = es;
    sh2[t] = (double)term;
    __syncthreads();
    for (int off = 512; off > 0; off >>= 1) {
        if (t < off) { sh1[t] += sh1[t + off]; sh2[t] += sh2[t + off]; }
        __syncthreads();
    }
    if (t == 0) {
        out[0] = 0.25f * (float)(sh1[0] / (double)NROWS);
        out[1 + QELEMS] = expf(-(float)sh2[0]);
    }
}

// ---------------- launch ----------------
extern "C" void kernel_launch(void* const* d_in, const int* in_sizes, int n_in,
                              void* d_out, int out_size) {
    const float* inp = (const float*)d_in[0];
    const float* emb = (const float*)d_in[1];
    float* out = (float*)d_out;

    cudaFuncSetAttribute(gemm_f16_kernel, cudaFuncAttributeMaxDynamicSharedMemorySize, SMEM_DYN);

    zero_kernel<<<1, 1024>>>();
    transpose_kernel<<<dim3(HWSZ / 32, DDIM / 32, BATCH), dim3(32, 8)>>>(inp);
    prep_e_kernel<<<KCODES, 256>>>(emb);
    gemm_f16_kernel<<<dim3(KCODES / 128, NROWS / 128), 256, SMEM_DYN>>>();
    epi_kernel<<<NROWS, 256>>>(inp, emb);
    scatter_kernel<<<dim3(HWSZ / 256, BATCH), 256>>>(emb, out + 1);
    finalize_kernel<<<1, 1024>>>(out);
}